// round 7
// baseline (speedup 1.0000x reference)
#include <cuda_runtime.h>
#include <cuda_fp16.h>
#include <cstdint>

#define NPIX (4 * 256 * 256)   // 262144 pixels
#define CDIM 192
#define SCALE 0.17677669529663689f

// ---------------- scratch (static device arrays; no runtime allocs) --------
__device__ __half g_xh [NPIX * CDIM];
__device__ __half g_q  [NPIX * CDIM];
__device__ __half g_k  [NPIX * CDIM];
__device__ __half g_v  [NPIX * CDIM];
__device__ __half g_ao [NPIX * CDIM];
__device__ __half g_t3a[NPIX * 32];
__device__ __half g_t3b[NPIX * 32];
__device__ __half g_t5a[NPIX * 16];
__device__ __half g_t5b[NPIX * 16];

__device__ __forceinline__ uint32_t pack_h2(float a, float b) {
    __half2 h = __floats2half2_rn(a, b);
    return *(uint32_t*)&h;
}

__device__ __forceinline__ void mma_f16_16x8x16(float* c, const uint32_t* a,
                                                const uint32_t* b) {
    asm volatile(
        "mma.sync.aligned.m16n8k16.row.col.f32.f16.f16.f32 "
        "{%0,%1,%2,%3}, {%4,%5,%6,%7}, {%8,%9}, {%0,%1,%2,%3};"
        : "+f"(c[0]), "+f"(c[1]), "+f"(c[2]), "+f"(c[3])
        : "r"(a[0]), "r"(a[1]), "r"(a[2]), "r"(a[3]), "r"(b[0]), "r"(b[1]));
}

// ---------------- fp32 -> fp16 prepass (x only) -----------------------------
__global__ __launch_bounds__(256)
void f2h_kernel(const float* __restrict__ in, __half* __restrict__ out)
{
    int i = blockIdx.x * blockDim.x + threadIdx.x;   // one uint4 (8 halves)
    float4 a = ((const float4*)in)[2 * i];
    float4 b = ((const float4*)in)[2 * i + 1];
    uint4 o;
    o.x = pack_h2(a.x, a.y); o.y = pack_h2(a.z, a.w);
    o.z = pack_h2(b.x, b.y); o.w = pack_h2(b.z, b.w);
    ((uint4*)out)[i] = o;
}

// ============================================================================
// Pipelined implicit-GEMM conv on fp16 mma.sync (fp32 accumulate).
// One CTA = one image row (256 output pixels) x BN output channels.
// Stages (kh, c0-chunk) are software-pipelined: next stage's gmem loads are
// issued into registers before the current stage's MMAs, double-buffered SMEM,
// one __syncthreads per stage.
// NT=256 for BN=64 (8 warps, 2x4), NT=128 for BN<=32 (4 warps x 64 rows).
// grid = (1024 rows, Ncols/BN).
// ============================================================================
template <int KS, int CIN, int BN, int OSTR, bool RELU, bool SPLIT,
          typename OutT, int NT>
__global__ __launch_bounds__(NT)
void conv_mma(const __half* __restrict__ X, const float* __restrict__ Wt,
              const float* __restrict__ bias, OutT* __restrict__ out0,
              OutT* __restrict__ out1, int cbase)
{
    constexpr int PAD = KS / 2;
    constexpr int AS_S = 264;          // A smem stride (uint32), %32 == 8
    constexpr int BS_S = KS * BN + 8;  // B smem stride, %32 in {8,24}
    constexpr int NCH = CIN / 16;
    constexpr int NSTAGE = KS * NCH;
    constexpr int SLAB = 256 + 2 * PAD;
    constexpr int MAXP = (SLAB + NT - 1) / NT;
    constexpr int NB = KS * BN * 8 / NT;
    static_assert((KS * BN * 8) % NT == 0, "B stage divisibility");

    __shared__ uint32_t As[2][8][AS_S];
    __shared__ uint32_t Bs[2][8][BS_S];

    const int tid = threadIdx.x;
    const int lane = tid & 31, warp = tid >> 5;
    const int grp = lane >> 2, thr4 = lane & 3;

    constexpr int NWARPS = NT / 32;
    constexpr int NW = (BN == 64) ? 2 : 1;   // warps along N
    constexpr int MW = NWARPS / NW;          // warps along M
    constexpr int WROWS = 256 / MW;          // 64
    constexpr int WCOLS = BN / NW;
    constexpr int MI = WROWS / 16;           // 4
    constexpr int NI = WCOLS / 8;
    const int mo = (NW == 2 ? (warp >> 1) : warp) * WROWS;
    const int no = (NW == 2 ? (warp & 1) : 0) * WCOLS;

    const int row = blockIdx.x;              // b*256 + h
    const int h = row & 255;
    const int pixbase = row << 8;
    const int n0 = blockIdx.y * BN;

    float acc[MI][NI][4];
#pragma unroll
    for (int i = 0; i < MI; i++)
#pragma unroll
        for (int j = 0; j < NI; j++)
#pragma unroll
            for (int r = 0; r < 4; r++) acc[i][j][r] = 0.0f;

    uint4 pa0[MAXP], pa1[MAXP];
    uint32_t pb[NB];

    // ---- prefetch stage s gmem -> registers ----
    auto prefetch = [&](int s) {
        const int kh = s / NCH;
        const int c0 = (s - kh * NCH) * 16;
        const int hs = h + kh - PAD;
        const bool vh = ((unsigned)hs < 256u);
        const int spix = (row - h + hs) << 8;
#pragma unroll
        for (int i = 0; i < MAXP; i++) {
            const int p = tid + i * NT;
            uint4 u0 = make_uint4(0, 0, 0, 0), u1 = make_uint4(0, 0, 0, 0);
            if (p < SLAB) {
                const int ws = p - PAD;
                if (vh && (unsigned)ws < 256u) {
                    const __half* src = X + (size_t)(spix + ws) * CIN + c0;
                    u0 = *(const uint4*)src;
                    u1 = *(const uint4*)(src + 8);
                }
            }
            pa0[i] = u0; pa1[i] = u1;
        }
#pragma unroll
        for (int i = 0; i < NB; i++) {
            const int idx = tid + i * NT;
            const int kw2 = idx / (BN * 8);
            const int rem = idx - kw2 * (BN * 8);
            const int j = rem >> 3, kp = rem & 7;
            const float* wsrc = Wt + (size_t)(n0 + j) * (CIN * KS * KS)
                                + (c0 + 2 * kp) * (KS * KS) + kh * KS + kw2;
            pb[i] = pack_h2(wsrc[0], wsrc[KS * KS]);
        }
    };
    // ---- store registers -> smem buffer ----
    auto store = [&](int buf) {
#pragma unroll
        for (int i = 0; i < MAXP; i++) {
            const int p = tid + i * NT;
            if (p < SLAB) {
                As[buf][0][p] = pa0[i].x; As[buf][1][p] = pa0[i].y;
                As[buf][2][p] = pa0[i].z; As[buf][3][p] = pa0[i].w;
                As[buf][4][p] = pa1[i].x; As[buf][5][p] = pa1[i].y;
                As[buf][6][p] = pa1[i].z; As[buf][7][p] = pa1[i].w;
            }
        }
#pragma unroll
        for (int i = 0; i < NB; i++) {
            const int idx = tid + i * NT;
            const int kw2 = idx / (BN * 8);
            const int rem = idx - kw2 * (BN * 8);
            const int j = rem >> 3, kp = rem & 7;
            Bs[buf][kp][kw2 * BN + j] = pb[i];
        }
    };
    // ---- MMA over one staged chunk ----
    auto compute = [&](int buf) {
#pragma unroll
        for (int kw = 0; kw < KS; kw++) {
            uint32_t a[MI][4], b[NI][2];
#pragma unroll
            for (int mi = 0; mi < MI; mi++) {
                const int col = mo + mi * 16 + grp + kw;
                a[mi][0] = As[buf][thr4][col];
                a[mi][1] = As[buf][thr4][col + 8];
                a[mi][2] = As[buf][thr4 + 4][col];
                a[mi][3] = As[buf][thr4 + 4][col + 8];
            }
#pragma unroll
            for (int ni = 0; ni < NI; ni++) {
                const int bc = kw * BN + no + ni * 8 + grp;
                b[ni][0] = Bs[buf][thr4][bc];
                b[ni][1] = Bs[buf][thr4 + 4][bc];
            }
#pragma unroll
            for (int mi = 0; mi < MI; mi++)
#pragma unroll
                for (int ni = 0; ni < NI; ni++)
                    mma_f16_16x8x16(acc[mi][ni], a[mi], b[ni]);
        }
    };

    prefetch(0);
    store(0);
    __syncthreads();
#pragma unroll 1
    for (int s = 0; s < NSTAGE; s++) {
        if (s + 1 < NSTAGE) prefetch(s + 1);
        compute(s & 1);
        if (s + 1 < NSTAGE) store((s + 1) & 1);
        __syncthreads();
    }

    // ---- epilogue ----
    OutT* dst;
    int cb, stride;
    if (SPLIT) {
        if (n0 < 64) { dst = out0; } else { dst = out1; }
        cb = cbase; stride = 192;
    } else { dst = out0; cb = n0; stride = OSTR; }

#pragma unroll
    for (int mi = 0; mi < MI; mi++) {
        size_t r0 = (size_t)(pixbase + mo + mi * 16 + grp);
        size_t r1 = r0 + 8;
#pragma unroll
        for (int ni = 0; ni < NI; ni++) {
            int colL = no + ni * 8 + 2 * thr4;
            float b0 = __ldg(&bias[n0 + colL]);
            float b1 = __ldg(&bias[n0 + colL + 1]);
            float v00 = acc[mi][ni][0] + b0, v01 = acc[mi][ni][1] + b1;
            float v10 = acc[mi][ni][2] + b0, v11 = acc[mi][ni][3] + b1;
            if (RELU) {
                v00 = v00 >= 0.f ? v00 : 0.2f * v00;
                v01 = v01 >= 0.f ? v01 : 0.2f * v01;
                v10 = v10 >= 0.f ? v10 : 0.2f * v10;
                v11 = v11 >= 0.f ? v11 : 0.2f * v11;
            }
            if (sizeof(OutT) == 2) {
                *(uint32_t*)&dst[r0 * stride + cb + colL] = pack_h2(v00, v01);
                *(uint32_t*)&dst[r1 * stride + cb + colL] = pack_h2(v10, v11);
            } else {
                *(float2*)&dst[r0 * stride + cb + colL] = make_float2(v00, v01);
                *(float2*)&dst[r1 * stride + cb + colL] = make_float2(v10, v11);
            }
        }
    }
}

// ============================================================================
// Window attention: fp16 in / fp16 out, fp32 compute.
// One 64-thread block per (window, head). grid = (6, 4096).
// ============================================================================
__global__ __launch_bounds__(64)
void attn_kernel(const __half* __restrict__ q, const __half* __restrict__ k,
                 const __half* __restrict__ v, const float* __restrict__ rpb,
                 __half* __restrict__ out)
{
    __shared__ float ks_[64][36];
    __shared__ float vs_[64][36];
    __shared__ float rs[225];

    const int hh = blockIdx.x;
    const int wi = blockIdx.y;
    const int n  = threadIdx.x;
    const int b  = wi >> 10;
    const int rem = wi & 1023;
    const int wh = rem >> 5, ww = rem & 31;
    const int r1 = n >> 3, c1 = n & 7;
    const int gh = wh * 8 + r1, gw = ww * 8 + c1;
    const size_t pix = (size_t)(b * 256 + gh) * 256 + gw;
    const int cb = hh * 32;

    for (int i = n; i < 225; i += 64) rs[i] = rpb[i * 6 + hh];

    float qr[32];
#pragma unroll
    for (int d8 = 0; d8 < 4; d8++) {
        uint4 ku = *(const uint4*)(k + pix * 192 + cb + d8 * 8);
        uint4 vu = *(const uint4*)(v + pix * 192 + cb + d8 * 8);
        uint4 qu = *(const uint4*)(q + pix * 192 + cb + d8 * 8);
        const __half2* kh2 = (const __half2*)&ku;
        const __half2* vh2 = (const __half2*)&vu;
        const __half2* qh2 = (const __half2*)&qu;
#pragma unroll
        for (int j = 0; j < 4; j++) {
            float2 kf = __half22float2(kh2[j]);
            float2 vf = __half22float2(vh2[j]);
            float2 qf = __half22float2(qh2[j]);
            ks_[n][d8 * 8 + 2 * j]     = kf.x;
            ks_[n][d8 * 8 + 2 * j + 1] = kf.y;
            vs_[n][d8 * 8 + 2 * j]     = vf.x;
            vs_[n][d8 * 8 + 2 * j + 1] = vf.y;
            qr[d8 * 8 + 2 * j]     = qf.x * SCALE;
            qr[d8 * 8 + 2 * j + 1] = qf.y * SCALE;
        }
    }
    __syncthreads();

    float s[64];
    float mx = -1e30f;
#pragma unroll
    for (int m = 0; m < 64; m++) {
        float dot = 0.f;
#pragma unroll
        for (int d4 = 0; d4 < 8; d4++) {
            float4 kk4 = *(const float4*)&ks_[m][d4 * 4];
            dot += qr[d4 * 4 + 0] * kk4.x;
            dot += qr[d4 * 4 + 1] * kk4.y;
            dot += qr[d4 * 4 + 2] * kk4.z;
            dot += qr[d4 * 4 + 3] * kk4.w;
        }
        int dr = r1 - (m >> 3) + 7;
        int dc = c1 - (m & 7) + 7;
        dot += rs[dr * 15 + dc];
        s[m] = dot;
        mx = fmaxf(mx, dot);
    }
    float sum = 0.f;
#pragma unroll
    for (int m = 0; m < 64; m++) {
        s[m] = __expf(s[m] - mx);
        sum += s[m];
    }
    const float inv = 1.0f / sum;

    float accv[32];
#pragma unroll
    for (int d = 0; d < 32; d++) accv[d] = 0.f;
#pragma unroll
    for (int m = 0; m < 64; m++) {
        float p = s[m];
#pragma unroll
        for (int d4 = 0; d4 < 8; d4++) {
            float4 vv = *(const float4*)&vs_[m][d4 * 4];
            accv[d4 * 4 + 0] += p * vv.x;
            accv[d4 * 4 + 1] += p * vv.y;
            accv[d4 * 4 + 2] += p * vv.z;
            accv[d4 * 4 + 3] += p * vv.w;
        }
    }
    const size_t opix = (size_t)wi * 64 + n;
    __half* op = out + opix * 192 + cb;
#pragma unroll
    for (int d8 = 0; d8 < 4; d8++) {
        uint4 o;
        o.x = pack_h2(accv[d8 * 8 + 0] * inv, accv[d8 * 8 + 1] * inv);
        o.y = pack_h2(accv[d8 * 8 + 2] * inv, accv[d8 * 8 + 3] * inv);
        o.z = pack_h2(accv[d8 * 8 + 4] * inv, accv[d8 * 8 + 5] * inv);
        o.w = pack_h2(accv[d8 * 8 + 6] * inv, accv[d8 * 8 + 7] * inv);
        *(uint4*)(op + d8 * 8) = o;
    }
}

// ============================================================================
extern "C" void kernel_launch(void* const* d_in, const int* in_sizes, int n_in,
                              void* d_out, int out_size)
{
    const float* x      = (const float*)d_in[0];
    const float* v_w    = (const float*)d_in[1];
    const float* v_b    = (const float*)d_in[2];
    const float* qk1_w  = (const float*)d_in[3];
    const float* qk1_b  = (const float*)d_in[4];
    const float* qk3_w1 = (const float*)d_in[5];
    const float* qk3_b1 = (const float*)d_in[6];
    const float* qk3_w2 = (const float*)d_in[7];
    const float* qk3_b2 = (const float*)d_in[8];
    const float* qk3_w3 = (const float*)d_in[9];
    const float* qk3_b3 = (const float*)d_in[10];
    const float* qk5_w1 = (const float*)d_in[11];
    const float* qk5_b1 = (const float*)d_in[12];
    const float* qk5_w2 = (const float*)d_in[13];
    const float* qk5_b2 = (const float*)d_in[14];
    const float* qk5_w3 = (const float*)d_in[15];
    const float* qk5_b3 = (const float*)d_in[16];
    const float* rpb    = (const float*)d_in[17];
    const float* proj_w = (const float*)d_in[18];
    const float* proj_b = (const float*)d_in[19];
    float* out = (float*)d_out;

    __half *xh, *q, *k, *v, *ao, *t3a, *t3b, *t5a, *t5b;
    cudaGetSymbolAddress((void**)&xh,  g_xh);
    cudaGetSymbolAddress((void**)&q,   g_q);
    cudaGetSymbolAddress((void**)&k,   g_k);
    cudaGetSymbolAddress((void**)&v,   g_v);
    cudaGetSymbolAddress((void**)&ao,  g_ao);
    cudaGetSymbolAddress((void**)&t3a, g_t3a);
    cudaGetSymbolAddress((void**)&t3b, g_t3b);
    cudaGetSymbolAddress((void**)&t5a, g_t5a);
    cudaGetSymbolAddress((void**)&t5b, g_t5b);

    // prepass: x -> fp16
    f2h_kernel<<<NPIX * CDIM / (256 * 8), 256>>>(x, xh);

    // v = conv1x1(x): N=192 in three 64-col blocks, stride 192
    conv_mma<1, 192, 64, 192, false, false, __half, 256><<<dim3(1024, 3), 256>>>(
        xh, v_w, v_b, v, nullptr, 0);
    // qk1: N=128, split q/k at cbase 0
    conv_mma<1, 192, 64, 192, false, true, __half, 256><<<dim3(1024, 2), 256>>>(
        xh, qk1_w, qk1_b, q, k, 0);
    // scale-3 branch
    conv_mma<3, 192, 32, 32, true, false, __half, 128><<<dim3(1024, 1), 128>>>(
        xh, qk3_w1, qk3_b1, t3a, nullptr, 0);
    conv_mma<1, 32, 32, 32, true, false, __half, 128><<<dim3(1024, 1), 128>>>(
        t3a, qk3_w2, qk3_b2, t3b, nullptr, 0);
    conv_mma<3, 32, 64, 192, false, true, __half, 256><<<dim3(1024, 2), 256>>>(
        t3b, qk3_w3, qk3_b3, q, k, 64);
    // scale-5 branch
    conv_mma<5, 192, 16, 16, true, false, __half, 128><<<dim3(1024, 1), 128>>>(
        xh, qk5_w1, qk5_b1, t5a, nullptr, 0);
    conv_mma<1, 16, 16, 16, true, false, __half, 128><<<dim3(1024, 1), 128>>>(
        t5a, qk5_w2, qk5_b2, t5b, nullptr, 0);
    conv_mma<5, 16, 64, 192, false, true, __half, 256><<<dim3(1024, 2), 256>>>(
        t5b, qk5_w3, qk5_b3, q, k, 128);
    // window attention (fp16 in/out)
    attn_kernel<<<dim3(6, 4096), 64>>>(q, k, v, rpb, ao);
    // output projection straight into d_out (fp32)
    conv_mma<1, 192, 64, 192, false, false, float, 256><<<dim3(1024, 3), 256>>>(
        ao, proj_w, proj_b, out, nullptr, 0);
}

// round 8
// speedup vs baseline: 1.4843x; 1.4843x over previous
#include <cuda_runtime.h>
#include <cuda_fp16.h>
#include <cstdint>

#define NPIX (4 * 256 * 256)   // 262144 pixels
#define CDIM 192
#define SCALE 0.17677669529663689f

// ---------------- scratch (static device arrays; no runtime allocs) --------
__device__ __half g_xh [NPIX * CDIM];
__device__ __half g_q  [NPIX * CDIM];
__device__ __half g_k  [NPIX * CDIM];
__device__ __half g_v  [NPIX * CDIM];
__device__ __half g_ao [NPIX * CDIM];
__device__ __half g_t3a[NPIX * 32];
__device__ __half g_t3b[NPIX * 32];
__device__ __half g_t5a[NPIX * 16];
__device__ __half g_t5b[NPIX * 16];
__device__ __half g_wh [319744];       // packed fp16 weights (incl. proj)

__device__ __forceinline__ uint32_t pack_h2(float a, float b) {
    __half2 h = __floats2half2_rn(a, b);
    return *(uint32_t*)&h;
}
__device__ __forceinline__ uint32_t smem_u32(const void* p) {
    uint32_t a;
    asm("{ .reg .u64 t; cvta.to.shared.u64 t, %1; cvt.u32.u64 %0, t; }"
        : "=r"(a) : "l"(p));
    return a;
}
__device__ __forceinline__ void cpa16(uint32_t dst, const void* src, int nbytes) {
    asm volatile("cp.async.cg.shared.global [%0], [%1], 16, %2;"
                 :: "r"(dst), "l"(src), "r"(nbytes));
}
__device__ __forceinline__ void cpa_commit() {
    asm volatile("cp.async.commit_group;" ::: "memory");
}
template <int N>
__device__ __forceinline__ void cpa_wait() {
    asm volatile("cp.async.wait_group %0;" :: "n"(N) : "memory");
}
__device__ __forceinline__ void mma_f16_16x8x16(float* c, const uint32_t* a,
                                                const uint32_t* b) {
    asm volatile(
        "mma.sync.aligned.m16n8k16.row.col.f32.f16.f16.f32 "
        "{%0,%1,%2,%3}, {%4,%5,%6,%7}, {%8,%9}, {%0,%1,%2,%3};"
        : "+f"(c[0]), "+f"(c[1]), "+f"(c[2]), "+f"(c[3])
        : "r"(a[0]), "r"(a[1]), "r"(a[2]), "r"(a[3]), "r"(b[0]), "r"(b[1]));
}
#define LDSM4(r0, r1, r2, r3, addr)                                           \
    asm volatile("ldmatrix.sync.aligned.m8n8.x4.shared.b16 {%0,%1,%2,%3}, [%4];" \
                 : "=r"(r0), "=r"(r1), "=r"(r2), "=r"(r3) : "r"(addr))
#define LDSM2(r0, r1, addr)                                                   \
    asm volatile("ldmatrix.sync.aligned.m8n8.x2.shared.b16 {%0,%1}, [%2];"    \
                 : "=r"(r0), "=r"(r1) : "r"(addr))

// ---------------- prepasses -------------------------------------------------
__global__ __launch_bounds__(256)
void f2h_kernel(const float* __restrict__ in, __half* __restrict__ out)
{
    int i = blockIdx.x * blockDim.x + threadIdx.x;   // one uint4 (8 halves)
    float4 a = ((const float4*)in)[2 * i];
    float4 b = ((const float4*)in)[2 * i + 1];
    uint4 o;
    o.x = pack_h2(a.x, a.y); o.y = pack_h2(a.z, a.w);
    o.z = pack_h2(b.x, b.y); o.w = pack_h2(b.z, b.w);
    ((uint4*)out)[i] = o;
}

// Pack OIHW fp32 weights -> fp16 [kh][cc][kw][cout][16ch] (cc = cin/16 chunk)
__global__ __launch_bounds__(256)
void pack_w(const float* __restrict__ W, __half* __restrict__ dst,
            int KS, int CIN, int COUT)
{
    int idx = blockIdx.x * 256 + threadIdx.x;
    int total = COUT * CIN * KS * KS;
    if (idx >= total) return;
    int ci = idx & 15;
    int t = idx >> 4;
    int cout = t % COUT; t /= COUT;
    int kw = t % KS; t /= KS;
    int cc = t % (CIN / 16); t /= (CIN / 16);
    int kh = t;
    dst[idx] = __float2half(
        W[((size_t)(cout * CIN + cc * 16 + ci) * KS + kh) * KS + kw]);
}

// ============================================================================
// Implicit-GEMM conv: fp16 mma.sync, cp.async staging, ldmatrix fragments.
// One CTA = one image row (256 output pixels) x BN output channels.
// SMEM: A = [slab pixel][16 halves] (stride 48B), B = [kw*BN+cout][16 halves].
// Double-buffered, cp.async pipelined, one LDSM.x4 / LDSM.x2 per fragment.
// grid = (1024 rows, CT/BN). CT = total couts in the packed weight tensor.
// ============================================================================
template <int KS, int CIN, int CT, int BN, int OSTR, bool RELU, bool SPLIT,
          typename OutT, int NT>
__global__ __launch_bounds__(NT)
void conv_mma(const __half* __restrict__ X, const __half* __restrict__ Wp,
              const float* __restrict__ bias, OutT* __restrict__ out0,
              OutT* __restrict__ out1, int cbase)
{
    constexpr int PAD = KS / 2;
    constexpr int NCH = CIN / 16;
    constexpr int NSTAGE = KS * NCH;
    constexpr int SLAB = 256 + 2 * PAD;
    constexpr int ABYTES = SLAB * 48;
    constexpr int BBYTES = KS * BN * 48;
    constexpr int BUFB = ABYTES + BBYTES;
    __shared__ alignas(16) char smem[2 * BUFB];

    const int tid = threadIdx.x;
    const int lane = tid & 31, warp = tid >> 5;
    const int grp = lane >> 2, thr4 = lane & 3;

    constexpr int NWARPS = NT / 32;
    constexpr int NW = (BN == 64) ? 2 : 1;
    constexpr int MW = NWARPS / NW;
    constexpr int WROWS = 256 / MW;          // 64
    constexpr int WCOLS = BN / NW;
    constexpr int MI = WROWS / 16;           // 4
    constexpr int NI = WCOLS / 8;
    static_assert(MI == 4, "tiling");
    const int mo = (NW == 2 ? (warp >> 1) : warp) * WROWS;
    const int no = (NW == 2 ? (warp & 1) : 0) * WCOLS;

    const int row = blockIdx.x;              // b*256 + h
    const int h = row & 255;
    const int pixbase = row << 8;
    const int n0 = blockIdx.y * BN;
    const uint32_t smbase = smem_u32(smem);

    float acc[MI][NI][4];
#pragma unroll
    for (int i = 0; i < MI; i++)
#pragma unroll
        for (int j = 0; j < NI; j++)
#pragma unroll
            for (int r = 0; r < 4; r++) acc[i][j][r] = 0.0f;

    auto issue = [&](int s) {
        const int kh = s / NCH;
        const int cc = s - kh * NCH;
        const int c0 = cc * 16;
        const int hs = h + kh - PAD;
        const bool vh = ((unsigned)hs < 256u);
        const int spix = (row - h + hs) << 8;
        const uint32_t aoff = smbase + (s & 1) * BUFB;
        for (int i = tid; i < SLAB * 2; i += NT) {
            const int p = i >> 1, hi = i & 1;
            const int ws = p - PAD;
            const bool ok = vh && ((unsigned)ws < 256u);
            const __half* src = ok
                ? X + ((size_t)(spix + ws) * CIN + c0 + hi * 8) : X;
            cpa16(aoff + p * 48 + hi * 16, src, ok ? 16 : 0);
        }
        const uint32_t boff = aoff + ABYTES;
        const __half* wb = Wp + (size_t)(kh * NCH + cc) * KS * CT * 16;
        for (int i = tid; i < KS * BN * 2; i += NT) {
            const int r = i >> 1, hi = i & 1;
            const int kw = r / BN, j = r - kw * BN;
            cpa16(boff + r * 48 + hi * 16,
                  wb + ((size_t)kw * CT + n0 + j) * 16 + hi * 8, 16);
        }
        cpa_commit();
    };

    auto compute = [&](int buf) {
        const uint32_t aB = smbase + buf * BUFB
                            + (lane & 15) * 48 + (lane >> 4) * 16;
        const uint32_t bB = smbase + buf * BUFB + ABYTES
                            + (lane & 7) * 48 + ((lane >> 3) & 1) * 16;
#pragma unroll
        for (int kw = 0; kw < KS; kw++) {
            uint32_t a[MI][4], b[NI][2];
#pragma unroll
            for (int mi = 0; mi < MI; mi++)
                LDSM4(a[mi][0], a[mi][1], a[mi][2], a[mi][3],
                      aB + (mo + mi * 16 + kw) * 48);
#pragma unroll
            for (int ni = 0; ni < NI; ni++)
                LDSM2(b[ni][0], b[ni][1], bB + (kw * BN + no + ni * 8) * 48);
#pragma unroll
            for (int mi = 0; mi < MI; mi++)
#pragma unroll
                for (int ni = 0; ni < NI; ni++)
                    mma_f16_16x8x16(acc[mi][ni], a[mi], b[ni]);
        }
    };

    issue(0);
#pragma unroll 1
    for (int s = 0; s < NSTAGE; s++) {
        if (s + 1 < NSTAGE) { issue(s + 1); cpa_wait<1>(); }
        else                { cpa_wait<0>(); }
        __syncthreads();
        compute(s & 1);
        __syncthreads();
    }

    // ---- epilogue ----
    OutT* dst;
    int cb, stride;
    if (SPLIT) {
        if (n0 < 64) { dst = out0; cb = cbase + n0; }
        else         { dst = out1; cb = cbase + n0 - 64; }
        stride = 192;
    } else { dst = out0; cb = n0; stride = OSTR; }

#pragma unroll
    for (int mi = 0; mi < MI; mi++) {
        size_t r0 = (size_t)(pixbase + mo + mi * 16 + grp);
        size_t r1 = r0 + 8;
#pragma unroll
        for (int ni = 0; ni < NI; ni++) {
            int colL = no + ni * 8 + 2 * thr4;
            float b0 = __ldg(&bias[n0 + colL]);
            float b1 = __ldg(&bias[n0 + colL + 1]);
            float v00 = acc[mi][ni][0] + b0, v01 = acc[mi][ni][1] + b1;
            float v10 = acc[mi][ni][2] + b0, v11 = acc[mi][ni][3] + b1;
            if (RELU) {
                v00 = v00 >= 0.f ? v00 : 0.2f * v00;
                v01 = v01 >= 0.f ? v01 : 0.2f * v01;
                v10 = v10 >= 0.f ? v10 : 0.2f * v10;
                v11 = v11 >= 0.f ? v11 : 0.2f * v11;
            }
            if (sizeof(OutT) == 2) {
                *(uint32_t*)&dst[r0 * stride + cb + colL] = pack_h2(v00, v01);
                *(uint32_t*)&dst[r1 * stride + cb + colL] = pack_h2(v10, v11);
            } else {
                *(float2*)&dst[r0 * stride + cb + colL] = make_float2(v00, v01);
                *(float2*)&dst[r1 * stride + cb + colL] = make_float2(v10, v11);
            }
        }
    }
}

// ============================================================================
// Window attention: fp16 in / fp16 out, fp32 compute.
// ============================================================================
__global__ __launch_bounds__(64)
void attn_kernel(const __half* __restrict__ q, const __half* __restrict__ k,
                 const __half* __restrict__ v, const float* __restrict__ rpb,
                 __half* __restrict__ out)
{
    __shared__ float ks_[64][36];
    __shared__ float vs_[64][36];
    __shared__ float rs[225];

    const int hh = blockIdx.x;
    const int wi = blockIdx.y;
    const int n  = threadIdx.x;
    const int b  = wi >> 10;
    const int rem = wi & 1023;
    const int wh = rem >> 5, ww = rem & 31;
    const int r1 = n >> 3, c1 = n & 7;
    const int gh = wh * 8 + r1, gw = ww * 8 + c1;
    const size_t pix = (size_t)(b * 256 + gh) * 256 + gw;
    const int cb = hh * 32;

    for (int i = n; i < 225; i += 64) rs[i] = rpb[i * 6 + hh];

    float qr[32];
#pragma unroll
    for (int d8 = 0; d8 < 4; d8++) {
        uint4 ku = *(const uint4*)(k + pix * 192 + cb + d8 * 8);
        uint4 vu = *(const uint4*)(v + pix * 192 + cb + d8 * 8);
        uint4 qu = *(const uint4*)(q + pix * 192 + cb + d8 * 8);
        const __half2* kh2 = (const __half2*)&ku;
        const __half2* vh2 = (const __half2*)&vu;
        const __half2* qh2 = (const __half2*)&qu;
#pragma unroll
        for (int j = 0; j < 4; j++) {
            float2 kf = __half22float2(kh2[j]);
            float2 vf = __half22float2(vh2[j]);
            float2 qf = __half22float2(qh2[j]);
            ks_[n][d8 * 8 + 2 * j]     = kf.x;
            ks_[n][d8 * 8 + 2 * j + 1] = kf.y;
            vs_[n][d8 * 8 + 2 * j]     = vf.x;
            vs_[n][d8 * 8 + 2 * j + 1] = vf.y;
            qr[d8 * 8 + 2 * j]     = qf.x * SCALE;
            qr[d8 * 8 + 2 * j + 1] = qf.y * SCALE;
        }
    }
    __syncthreads();

    float s[64];
    float mx = -1e30f;
#pragma unroll
    for (int m = 0; m < 64; m++) {
        float dot = 0.f;
#pragma unroll
        for (int d4 = 0; d4 < 8; d4++) {
            float4 kk4 = *(const float4*)&ks_[m][d4 * 4];
            dot += qr[d4 * 4 + 0] * kk4.x;
            dot += qr[d4 * 4 + 1] * kk4.y;
            dot += qr[d4 * 4 + 2] * kk4.z;
            dot += qr[d4 * 4 + 3] * kk4.w;
        }
        int dr = r1 - (m >> 3) + 7;
        int dc = c1 - (m & 7) + 7;
        dot += rs[dr * 15 + dc];
        s[m] = dot;
        mx = fmaxf(mx, dot);
    }
    float sum = 0.f;
#pragma unroll
    for (int m = 0; m < 64; m++) {
        s[m] = __expf(s[m] - mx);
        sum += s[m];
    }
    const float inv = 1.0f / sum;

    float accv[32];
#pragma unroll
    for (int d = 0; d < 32; d++) accv[d] = 0.f;
#pragma unroll
    for (int m = 0; m < 64; m++) {
        float p = s[m];
#pragma unroll
        for (int d4 = 0; d4 < 8; d4++) {
            float4 vv = *(const float4*)&vs_[m][d4 * 4];
            accv[d4 * 4 + 0] += p * vv.x;
            accv[d4 * 4 + 1] += p * vv.y;
            accv[d4 * 4 + 2] += p * vv.z;
            accv[d4 * 4 + 3] += p * vv.w;
        }
    }
    const size_t opix = (size_t)wi * 64 + n;
    __half* op = out + opix * 192 + cb;
#pragma unroll
    for (int d8 = 0; d8 < 4; d8++) {
        uint4 o;
        o.x = pack_h2(accv[d8 * 8 + 0] * inv, accv[d8 * 8 + 1] * inv);
        o.y = pack_h2(accv[d8 * 8 + 2] * inv, accv[d8 * 8 + 3] * inv);
        o.z = pack_h2(accv[d8 * 8 + 4] * inv, accv[d8 * 8 + 5] * inv);
        o.w = pack_h2(accv[d8 * 8 + 6] * inv, accv[d8 * 8 + 7] * inv);
        *(uint4*)(op + d8 * 8) = o;
    }
}

// ============================================================================
extern "C" void kernel_launch(void* const* d_in, const int* in_sizes, int n_in,
                              void* d_out, int out_size)
{
    const float* x      = (const float*)d_in[0];
    const float* v_w    = (const float*)d_in[1];
    const float* v_b    = (const float*)d_in[2];
    const float* qk1_w  = (const float*)d_in[3];
    const float* qk1_b  = (const float*)d_in[4];
    const float* qk3_w1 = (const float*)d_in[5];
    const float* qk3_b1 = (const float*)d_in[6];
    const float* qk3_w2 = (const float*)d_in[7];
    const float* qk3_b2 = (const float*)d_in[8];
    const float* qk3_w3 = (const float*)d_in[9];
    const float* qk3_b3 = (const float*)d_in[10];
    const float* qk5_w1 = (const float*)d_in[11];
    const float* qk5_b1 = (const float*)d_in[12];
    const float* qk5_w2 = (const float*)d_in[13];
    const float* qk5_b2 = (const float*)d_in[14];
    const float* qk5_w3 = (const float*)d_in[15];
    const float* qk5_b3 = (const float*)d_in[16];
    const float* rpb    = (const float*)d_in[17];
    const float* proj_w = (const float*)d_in[18];
    const float* proj_b = (const float*)d_in[19];
    float* out = (float*)d_out;

    __half *xh, *q, *k, *v, *ao, *t3a, *t3b, *t5a, *t5b, *wh;
    cudaGetSymbolAddress((void**)&xh,  g_xh);
    cudaGetSymbolAddress((void**)&q,   g_q);
    cudaGetSymbolAddress((void**)&k,   g_k);
    cudaGetSymbolAddress((void**)&v,   g_v);
    cudaGetSymbolAddress((void**)&ao,  g_ao);
    cudaGetSymbolAddress((void**)&t3a, g_t3a);
    cudaGetSymbolAddress((void**)&t3b, g_t3b);
    cudaGetSymbolAddress((void**)&t5a, g_t5a);
    cudaGetSymbolAddress((void**)&t5b, g_t5b);
    cudaGetSymbolAddress((void**)&wh,  g_wh);

    // packed weight offsets (halves)
    const int O_V = 0, O_Q1 = 36864, O_3W1 = 61440, O_3W2 = 116736,
              O_3W3 = 117760, O_5W1 = 154624, O_5W2 = 231424, O_5W3 = 231680,
              O_PJ = 282880;

    auto nb = [](int n) { return (n + 255) / 256; };
    // prepasses: x -> fp16, weights -> packed fp16
    f2h_kernel<<<NPIX * CDIM / (256 * 8), 256>>>(x, xh);
    pack_w<<<nb(36864), 256>>>(v_w,    wh + O_V,   1, 192, 192);
    pack_w<<<nb(24576), 256>>>(qk1_w,  wh + O_Q1,  1, 192, 128);
    pack_w<<<nb(55296), 256>>>(qk3_w1, wh + O_3W1, 3, 192, 32);
    pack_w<<<nb(1024),  256>>>(qk3_w2, wh + O_3W2, 1, 32, 32);
    pack_w<<<nb(36864), 256>>>(qk3_w3, wh + O_3W3, 3, 32, 128);
    pack_w<<<nb(76800), 256>>>(qk5_w1, wh + O_5W1, 5, 192, 16);
    pack_w<<<nb(256),   256>>>(qk5_w2, wh + O_5W2, 1, 16, 16);
    pack_w<<<nb(51200), 256>>>(qk5_w3, wh + O_5W3, 5, 16, 128);
    pack_w<<<nb(36864), 256>>>(proj_w, wh + O_PJ,  1, 192, 192);

    // v = conv1x1(x): N=192 in three 64-col blocks, stride 192
    conv_mma<1, 192, 192, 64, 192, false, false, __half, 256>
        <<<dim3(1024, 3), 256>>>(xh, wh + O_V, v_b, v, nullptr, 0);
    // qk1: N=128, split q/k at cbase 0
    conv_mma<1, 192, 128, 64, 192, false, true, __half, 256>
        <<<dim3(1024, 2), 256>>>(xh, wh + O_Q1, qk1_b, q, k, 0);
    // scale-3 branch
    conv_mma<3, 192, 32, 32, 32, true, false, __half, 128>
        <<<dim3(1024, 1), 128>>>(xh, wh + O_3W1, qk3_b1, t3a, nullptr, 0);
    conv_mma<1, 32, 32, 32, 32, true, false, __half, 128>
        <<<dim3(1024, 1), 128>>>(t3a, wh + O_3W2, qk3_b2, t3b, nullptr, 0);
    conv_mma<3, 32, 128, 64, 192, false, true, __half, 256>
        <<<dim3(1024, 2), 256>>>(t3b, wh + O_3W3, qk3_b3, q, k, 64);
    // scale-5 branch
    conv_mma<5, 192, 16, 16, 16, true, false, __half, 128>
        <<<dim3(1024, 1), 128>>>(xh, wh + O_5W1, qk5_b1, t5a, nullptr, 0);
    conv_mma<1, 16, 16, 16, 16, true, false, __half, 128>
        <<<dim3(1024, 1), 128>>>(t5a, wh + O_5W2, qk5_b2, t5b, nullptr, 0);
    conv_mma<5, 16, 128, 32, 192, false, true, __half, 128>
        <<<dim3(1024, 4), 128>>>(t5b, wh + O_5W3, qk5_b3, q, k, 128);
    // window attention (fp16 in/out)
    attn_kernel<<<dim3(6, 4096), 64>>>(q, k, v, rpb, ao);
    // output projection straight into d_out (fp32)
    conv_mma<1, 192, 192, 64, 192, false, false, float, 256>
        <<<dim3(1024, 3), 256>>>(ao, wh + O_PJ, proj_b, out, nullptr, 0);
}